// round 1
// baseline (speedup 1.0000x reference)
#include <cuda_runtime.h>
#include <cstdint>

// Problem constants (fixed by the reference)
// patches: [N=128, C=4, P=32, P, P] f32
// vol:     [B=2,  C=4, H=128, H, H] f32
// centers: [N, 3] i32 ; lower = center - P/2
#define PW        0.5f
#define N_PATCH   128
#define C_DIM     4
#define P_DIM     32
#define H_DIM     128
#define B_DIM     2
#define NPB       (N_PATCH / B_DIM)   // 64 patches per batch

// H^2 = 16384, H^3 = 2097152, C*H^3 = 8388608

__global__ void pi_scale_kernel(const float4* __restrict__ vol,
                                float4* __restrict__ out, int n4) {
    int i = blockIdx.x * blockDim.x + threadIdx.x;
    if (i < n4) {
        float4 v = vol[i];
        v.x *= (1.0f - PW);
        v.y *= (1.0f - PW);
        v.z *= (1.0f - PW);
        v.w *= (1.0f - PW);
        out[i] = v;
    }
}

// One thread per float4 of the patches tensor: N*C*P*P*(P/4) = 4,194,304 threads.
__global__ void pi_scatter_kernel(const float* __restrict__ patches,
                                  const int* __restrict__ centers,
                                  float* __restrict__ out) {
    unsigned tid = blockIdx.x * blockDim.x + threadIdx.x;

    // decode [n][c][i][j][k4] ; k4 in [0,8)
    unsigned k4 = tid & 7u;
    unsigned t  = tid >> 3;
    unsigned j  = t & 31u;  t >>= 5;
    unsigned i  = t & 31u;  t >>= 5;
    unsigned c  = t & 3u;
    unsigned n  = t >> 2;

    float4 p = reinterpret_cast<const float4*>(patches)[tid];

    int lo0 = __ldg(&centers[n * 3 + 0]) - (P_DIM / 2);
    int lo1 = __ldg(&centers[n * 3 + 1]) - (P_DIM / 2);
    int lo2 = __ldg(&centers[n * 3 + 2]) - (P_DIM / 2);

    unsigned b = n / NPB;  // n >> 6

    size_t base = ((size_t)b * C_DIM + c) * (size_t)(H_DIM * H_DIM * H_DIM)
                + (size_t)(lo0 + (int)i) * (H_DIM * H_DIM)
                + (size_t)(lo1 + (int)j) * H_DIM
                + (size_t)lo2 + k4 * 4u;

    float* o = out + base;
    atomicAdd(o + 0, p.x * PW);
    atomicAdd(o + 1, p.y * PW);
    atomicAdd(o + 2, p.z * PW);
    atomicAdd(o + 3, p.w * PW);
}

extern "C" void kernel_launch(void* const* d_in, const int* in_sizes, int n_in,
                              void* d_out, int out_size) {
    const float* patches = (const float*)d_in[0];
    const float* vol     = (const float*)d_in[1];
    const int*   centers = (const int*)d_in[2];
    float*       out     = (float*)d_out;

    // 1) out = vol * (1 - PW)
    int n4 = out_size / 4;  // 16,777,216 floats -> 4,194,304 float4
    {
        int threads = 256;
        int blocks = (n4 + threads - 1) / threads;
        pi_scale_kernel<<<blocks, threads>>>((const float4*)vol, (float4*)out, n4);
    }

    // 2) scatter-add 0.5*patches
    {
        unsigned total = N_PATCH * C_DIM * P_DIM * P_DIM * (P_DIM / 4);  // 4,194,304
        int threads = 256;
        int blocks = total / threads;
        pi_scatter_kernel<<<blocks, threads>>>(patches, centers, out);
    }
}

// round 2
// speedup vs baseline: 1.2724x; 1.2724x over previous
#include <cuda_runtime.h>
#include <cstdint>

// patches: [N=128, C=4, P=32, P, P] f32
// vol:     [B=2,  C=4, H=128, H, H] f32
// centers: [N, 3] i32 ; lower = center - P/2 (in [0, 96])
#define PW        0.5f
#define N_PATCH   128
#define C_DIM     4
#define P_DIM     32
#define H_DIM     128
#define B_DIM     2

#define ROWS      (N_PATCH * C_DIM * P_DIM * P_DIM)   // 524288 rows of 32 floats
#define QPR       9                                    // aligned quads per row (max)
#define TOTAL     (ROWS * QPR)                         // 4,718,592 threads

__global__ void pi_scale_kernel(const float4* __restrict__ vol,
                                float4* __restrict__ out, int n4) {
    int i = blockIdx.x * blockDim.x + threadIdx.x;
    if (i < n4) {
        float4 v = vol[i];
        v.x *= (1.0f - PW);
        v.y *= (1.0f - PW);
        v.z *= (1.0f - PW);
        v.w *= (1.0f - PW);
        out[i] = v;
    }
}

// One thread per output-aligned float4 quad intersecting a patch row.
// Row = [n][c][i][j] (32 contiguous d-floats in both patch and output).
__global__ void pi_scatter_kernel(const float* __restrict__ patches,
                                  const int* __restrict__ centers,
                                  float* __restrict__ out) {
    unsigned tid = blockIdx.x * blockDim.x + threadIdx.x;
    if (tid >= TOTAL) return;

    unsigned row = tid / QPR;          // mul-shift, cheap
    unsigned q   = tid - row * QPR;    // 0..8

    // decode row -> [n][c][i][j]
    unsigned j = row & 31u;
    unsigned t = row >> 5;
    unsigned i = t & 31u;  t >>= 5;
    unsigned c = t & 3u;
    unsigned n = t >> 2;

    int lo0 = __ldg(&centers[n * 3 + 0]) - (P_DIM / 2);
    int lo1 = __ldg(&centers[n * 3 + 1]) - (P_DIM / 2);
    int lo2 = __ldg(&centers[n * 3 + 2]) - (P_DIM / 2);

    unsigned b = n >> 6;  // 64 patches per batch

    // output row base (multiple of H=128 floats -> 16B aligned)
    size_t obase = ((size_t)(b * C_DIM + c)) * (size_t)(H_DIM * H_DIM * H_DIM)
                 + (size_t)(lo0 + (int)i) * (H_DIM * H_DIM)
                 + (size_t)(lo1 + (int)j) * H_DIM;

    int Q  = (lo2 >> 2) + (int)q;      // aligned quad index within the d-line
    int k0 = (Q << 2) - lo2;           // patch k for component 0, in [-3, 35]

    const float* prow = patches + (size_t)row * P_DIM;
    float* o = out + obase + ((size_t)Q << 2);

    if (k0 >= 0 && k0 + 3 < P_DIM) {
        // fully interior quad: one 16B vector reduction
        float v0 = prow[k0]     * PW;
        float v1 = prow[k0 + 1] * PW;
        float v2 = prow[k0 + 2] * PW;
        float v3 = prow[k0 + 3] * PW;
        asm volatile("red.global.add.v4.f32 [%0], {%1, %2, %3, %4};"
                     :: "l"(o), "f"(v0), "f"(v1), "f"(v2), "f"(v3)
                     : "memory");
    } else {
        // edge quad: scalar reds on valid components only
        #pragma unroll
        for (int s = 0; s < 4; s++) {
            int k = k0 + s;
            if (k >= 0 && k < P_DIM)
                atomicAdd(o + s, prow[k] * PW);
        }
    }
}

extern "C" void kernel_launch(void* const* d_in, const int* in_sizes, int n_in,
                              void* d_out, int out_size) {
    const float* patches = (const float*)d_in[0];
    const float* vol     = (const float*)d_in[1];
    const int*   centers = (const int*)d_in[2];
    float*       out     = (float*)d_out;

    // 1) out = vol * (1 - PW)
    int n4 = out_size / 4;  // 4,194,304 float4
    {
        int threads = 256;
        int blocks = (n4 + threads - 1) / threads;
        pi_scale_kernel<<<blocks, threads>>>((const float4*)vol, (float4*)out, n4);
    }

    // 2) scatter-add 0.5*patches with vectorized reductions
    {
        int threads = 256;
        int blocks = (TOTAL + threads - 1) / threads;
        pi_scatter_kernel<<<blocks, threads>>>(patches, centers, out);
    }
}

// round 3
// speedup vs baseline: 1.4785x; 1.1620x over previous
#include <cuda_runtime.h>
#include <cstdint>

// patches: [N=128, C=4, P=32, P, P] f32
// vol:     [B=2,  C=4, H=128, H, H] f32
// centers: [N, 3] i32 ; lower = center - P/2 (in [0, 96])
#define PW        0.5f
#define N_PATCH   128
#define C_DIM     4
#define P_DIM     32
#define H_DIM     128

#define ROWS      (N_PATCH * C_DIM * P_DIM * P_DIM)   // 524288 rows of 32 floats
#define QPR       9                                    // output-aligned quads per row
#define TOTAL     (ROWS * QPR)                         // 4,718,592 threads

__global__ void pi_scale_kernel(const float4* __restrict__ vol,
                                float4* __restrict__ out, int n4) {
    int i = blockIdx.x * blockDim.x + threadIdx.x;
    if (i < n4) {
        float4 v = vol[i];
        v.x *= (1.0f - PW);
        v.y *= (1.0f - PW);
        v.z *= (1.0f - PW);
        v.w *= (1.0f - PW);
        out[i] = v;
    }
}

// One thread per output-aligned float4 quad intersecting a patch row.
// Row = [n][c][i][j]; both patch row (32 floats) and output d-line are contiguous.
// The misaligned patch window [4q-s, 4q-s+3] is assembled from the two aligned
// patch quads p4[q-1], p4[q] (zero-filled at the edges), then one red.v4.
__global__ void pi_scatter_kernel(const float* __restrict__ patches,
                                  const int* __restrict__ centers,
                                  float* __restrict__ out) {
    unsigned tid = blockIdx.x * blockDim.x + threadIdx.x;
    if (tid >= TOTAL) return;

    unsigned row = tid / QPR;          // mul-shift
    unsigned q   = tid - row * QPR;    // 0..8

    // decode row -> [n][c][i][j]
    unsigned j = row & 31u;
    unsigned t = row >> 5;
    unsigned i = t & 31u;  t >>= 5;
    unsigned c = t & 3u;
    unsigned n = t >> 2;

    int lo0 = __ldg(&centers[n * 3 + 0]) - (P_DIM / 2);
    int lo1 = __ldg(&centers[n * 3 + 1]) - (P_DIM / 2);
    int lo2 = __ldg(&centers[n * 3 + 2]) - (P_DIM / 2);

    unsigned s = (unsigned)lo2 & 3u;   // warp-uniform shift (same n across warp)
    if (s == 0u && q == 8u) return;    // only thread that would land out of bounds

    unsigned b = n >> 6;               // 64 patches per batch

    size_t obase = ((size_t)(b * C_DIM + c)) * (size_t)(H_DIM * H_DIM * H_DIM)
                 + (size_t)(lo0 + (int)i) * (H_DIM * H_DIM)
                 + (size_t)(lo1 + (int)j) * H_DIM;

    int Q = (lo2 >> 2) + (int)q;       // aligned output quad index (0..31)
    float* o = out + obase + ((size_t)Q << 2);

    const float4* p4 = reinterpret_cast<const float4*>(patches) + (size_t)row * 8;
    float4 qL = (q >= 1u) ? __ldg(p4 + q - 1) : make_float4(0.f, 0.f, 0.f, 0.f);
    float4 qR = (q <= 7u) ? __ldg(p4 + q)     : make_float4(0.f, 0.f, 0.f, 0.f);

    float a0, a1, a2, a3;
    switch (s) {                        // warp-uniform: no divergence
        case 0u:  a0 = qR.x; a1 = qR.y; a2 = qR.z; a3 = qR.w; break;
        case 1u:  a0 = qL.w; a1 = qR.x; a2 = qR.y; a3 = qR.z; break;
        case 2u:  a0 = qL.z; a1 = qL.w; a2 = qR.x; a3 = qR.y; break;
        default:  a0 = qL.y; a1 = qL.z; a2 = qL.w; a3 = qR.x; break;
    }

    asm volatile("red.global.add.v4.f32 [%0], {%1, %2, %3, %4};"
                 :: "l"(o), "f"(a0 * PW), "f"(a1 * PW), "f"(a2 * PW), "f"(a3 * PW)
                 : "memory");
}

extern "C" void kernel_launch(void* const* d_in, const int* in_sizes, int n_in,
                              void* d_out, int out_size) {
    const float* patches = (const float*)d_in[0];
    const float* vol     = (const float*)d_in[1];
    const int*   centers = (const int*)d_in[2];
    float*       out     = (float*)d_out;

    // 1) out = vol * (1 - PW)
    int n4 = out_size / 4;  // 4,194,304 float4
    {
        int threads = 256;
        int blocks = (n4 + threads - 1) / threads;
        pi_scale_kernel<<<blocks, threads>>>((const float4*)vol, (float4*)out, n4);
    }

    // 2) scatter-add 0.5*patches with vectorized loads + vectorized reductions
    {
        int threads = 256;
        int blocks = (TOTAL + threads - 1) / threads;
        pi_scatter_kernel<<<blocks, threads>>>(patches, centers, out);
    }
}